// round 7
// baseline (speedup 1.0000x reference)
#include <cuda_runtime.h>
#include <cuda_fp16.h>
#include <math.h>
#include <stdint.h>

#define BATCH 512
#define NP    64
#define CIN   512
#define HID   512
#define EMB   512
#define NCLS  96
#define TT    30

// ---------------- scratch (device globals; no allocations) ----------------
__device__ __half g_featcvt[(size_t)BATCH * NP * CIN];
__device__ float  g_feats[(size_t)BATCH * NP * HID];    // fp32 (attention)
__device__ __half g_emb[(size_t)TT * BATCH * EMB];
__device__ float  g_pre[(size_t)TT * BATCH * 1024];     // [lpre | xpre] fp32
__device__ __half g_hist[(size_t)TT * BATCH * HID];
__device__ __half g_hbuf[2][BATCH * HID];
__device__ float  g_c[BATCH * HID];
__device__ float  g_logits[BATCH * HID];
__device__ __half g_ctx[BATCH * HID];
__device__ __half g_x[BATCH * HID];
__device__ __half g_Wg[(size_t)2048 * 1024];            // gate-interleaved
__device__ float  g_bg[2048];
__device__ __half g_Wlx[(size_t)1024 * 512];            // [WaE ; WcC]
__device__ float  g_blx[1024];
#define OFF_WFC 0
#define OFF_WA  (512 * 512)
#define OFF_WC  (OFF_WA + 512 * 1024)
#define OFF_WO  (OFF_WC + 512 * 1024)
__device__ __half g_wcvt[OFF_WO + 96 * 512];

__device__ __forceinline__ float fsig(float x) {
    return __fdividef(1.f, 1.f + __expf(-x));
}
__device__ __forceinline__ float ftanh(float x) {
    x = fminf(fmaxf(x, -15.f), 15.f);
    float t = __expf(2.f * x);
    return __fdividef(t - 1.f, t + 1.f);
}

__device__ __forceinline__ void cp16(uint32_t dst, const void* src) {
    asm volatile("cp.async.cg.shared.global [%0], [%1], 16;" :: "r"(dst), "l"(src));
}
__device__ __forceinline__ void cp_commit() { asm volatile("cp.async.commit_group;"); }
template <int N>
__device__ __forceinline__ void cp_wait() { asm volatile("cp.async.wait_group %0;" :: "n"(N)); }

// ------------- FP16 GEMM (fp32 accum), cp.async + frag double-buffer ------
// A logically [M,K] half, split along K. B [N,K] half rows at B + n*ldb + boff.
// MODE 0: float C = acc (+bias)(+addend[ldadd])
// MODE 3: half  C = acc (+addend[ldadd])
// MODE 1: fused LSTM epilogue (half h_out, g_hist)
// MODE 2: permuted fp32 out-projection write
template <int BM, int BN, int BK, int WARPS_M, int WARPS_N, int MODE>
__global__ void __launch_bounds__(WARPS_M * WARPS_N * 32)
gemm(const __half* __restrict__ A1, int lda1, int K1,
     const __half* __restrict__ A2, int lda2, int K,
     const __half* __restrict__ B, int ldb, int boff,
     const float* __restrict__ bias,
     const float* __restrict__ addend, int ldadd,
     void* __restrict__ Cv, int ldc, __half* __restrict__ h_out, int t)
{
    constexpr int S = 3, PAD = 8, ROWF = BK + PAD;        // halfs
    constexpr int THREADS = WARPS_M * WARPS_N * 32;
    constexpr int WM = BM / WARPS_M, WN = BN / WARPS_N;
    constexpr int M_SUB = WM / 16, N_SUB = WN / 8;
    constexpr int BK8 = BK / 8;
    constexpr int AV = (BM * BK) / (8 * THREADS);
    constexpr int BV = (BN * BK) / (8 * THREADS);
    constexpr int ASTR = BM * ROWF;                       // halfs per A stage
    constexpr int BSTR = BN * ROWF;
    constexpr int KS = BK / 16;

    extern __shared__ __half sh[];
    const uint32_t smem_u = (uint32_t)__cvta_generic_to_shared(sh);

    const int bm = blockIdx.y * BM;
    const int bn = blockIdx.x * BN;
    const int tid = threadIdx.x;
    const int wid = tid >> 5;
    const int lane = tid & 31;
    const int gid = lane >> 2;
    const int tig = lane & 3;
    const int warpM = wid % WARPS_M;
    const int warpN = wid / WARPS_M;

    float acc[M_SUB][N_SUB][4];
#pragma unroll
    for (int i = 0; i < M_SUB; i++)
#pragma unroll
        for (int j = 0; j < N_SUB; j++)
#pragma unroll
            for (int q = 0; q < 4; q++) acc[i][j][q] = 0.f;

    auto issue = [&](int stg, int k0) {
        const __half* Ap; int lda, kc;
        if (k0 < K1) { Ap = A1; lda = lda1; kc = k0; }
        else         { Ap = A2; lda = lda2; kc = k0 - K1; }
        uint32_t ab = smem_u + (uint32_t)(stg * ASTR) * 2u;
#pragma unroll
        for (int i = 0; i < AV; i++) {
            int idx = tid + i * THREADS;
            int r = idx / BK8, c8 = idx % BK8;
            cp16(ab + (uint32_t)(r * ROWF + c8 * 8) * 2u,
                 Ap + (size_t)(bm + r) * lda + kc + c8 * 8);
        }
        uint32_t bb = smem_u + (uint32_t)(S * ASTR + stg * BSTR) * 2u;
#pragma unroll
        for (int i = 0; i < BV; i++) {
            int idx = tid + i * THREADS;
            int r = idx / BK8, c8 = idx % BK8;
            cp16(bb + (uint32_t)(r * ROWF + c8 * 8) * 2u,
                 B + (size_t)(bn + r) * ldb + boff + k0 + c8 * 8);
        }
    };

    const int NK = K / BK;
    issue(0, 0);  cp_commit();
    issue(1, BK); cp_commit();

    uint32_t afr[2][M_SUB][4];
    uint32_t bfr[2][N_SUB][2];

    auto ldfrag = [&](const __half* As, const __half* Bs, int buf, int kb) {
#pragma unroll
        for (int mt = 0; mt < M_SUB; mt++) {
            int r0 = warpM * WM + mt * 16 + gid;
            afr[buf][mt][0] = *(const uint32_t*)(As + r0 * ROWF + kb + 2 * tig);
            afr[buf][mt][1] = *(const uint32_t*)(As + (r0 + 8) * ROWF + kb + 2 * tig);
            afr[buf][mt][2] = *(const uint32_t*)(As + r0 * ROWF + kb + 2 * tig + 8);
            afr[buf][mt][3] = *(const uint32_t*)(As + (r0 + 8) * ROWF + kb + 2 * tig + 8);
        }
#pragma unroll
        for (int nt = 0; nt < N_SUB; nt++) {
            int c0 = warpN * WN + nt * 8 + gid;
            bfr[buf][nt][0] = *(const uint32_t*)(Bs + c0 * ROWF + kb + 2 * tig);
            bfr[buf][nt][1] = *(const uint32_t*)(Bs + c0 * ROWF + kb + 2 * tig + 8);
        }
    };

    for (int k = 0; k < NK; k++) {
        cp_wait<1>();
        __syncthreads();
        int kn = k + S - 1;
        if (kn < NK) issue(kn % S, kn * BK);
        cp_commit();

        const __half* As = sh + (k % S) * ASTR;
        const __half* Bs = sh + S * ASTR + (k % S) * BSTR;

        ldfrag(As, Bs, 0, 0);

#pragma unroll
        for (int ks = 0; ks < KS; ks++) {
            const int cur = ks & 1, nxt = cur ^ 1;
            if (ks < KS - 1) ldfrag(As, Bs, nxt, (ks + 1) * 16);
#pragma unroll
            for (int nt = 0; nt < N_SUB; nt++) {
#pragma unroll
                for (int mt = 0; mt < M_SUB; mt++) {
                    asm volatile(
                        "mma.sync.aligned.m16n8k16.row.col.f32.f16.f16.f32 "
                        "{%0,%1,%2,%3}, {%4,%5,%6,%7}, {%8,%9}, {%0,%1,%2,%3};"
                        : "+f"(acc[mt][nt][0]), "+f"(acc[mt][nt][1]),
                          "+f"(acc[mt][nt][2]), "+f"(acc[mt][nt][3])
                        : "r"(afr[cur][mt][0]), "r"(afr[cur][mt][1]),
                          "r"(afr[cur][mt][2]), "r"(afr[cur][mt][3]),
                          "r"(bfr[cur][nt][0]), "r"(bfr[cur][nt][1]));
                }
            }
        }
    }

    if constexpr (MODE == 0) {
        float* C = (float*)Cv;
#pragma unroll
        for (int mt = 0; mt < M_SUB; mt++) {
#pragma unroll
            for (int nt = 0; nt < N_SUB; nt++) {
                int row0 = bm + warpM * WM + mt * 16 + gid;
                int col  = bn + warpN * WN + nt * 8 + 2 * tig;
                float bx = 0.f, by = 0.f;
                if (bias) { float2 bv = *(const float2*)(bias + col); bx = bv.x; by = bv.y; }
                float a0x = 0.f, a0y = 0.f, a1x = 0.f, a1y = 0.f;
                if (addend) {
                    float2 v = *(const float2*)(addend + (size_t)row0 * ldadd + col);
                    a0x = v.x; a0y = v.y;
                    float2 w = *(const float2*)(addend + (size_t)(row0 + 8) * ldadd + col);
                    a1x = w.x; a1y = w.y;
                }
                float2 v0 = { acc[mt][nt][0] + bx + a0x, acc[mt][nt][1] + by + a0y };
                float2 v1 = { acc[mt][nt][2] + bx + a1x, acc[mt][nt][3] + by + a1y };
                *(float2*)(C + (size_t)row0 * ldc + col) = v0;
                *(float2*)(C + (size_t)(row0 + 8) * ldc + col) = v1;
            }
        }
    } else if constexpr (MODE == 3) {
        __half* C = (__half*)Cv;
#pragma unroll
        for (int mt = 0; mt < M_SUB; mt++) {
#pragma unroll
            for (int nt = 0; nt < N_SUB; nt++) {
                int row0 = bm + warpM * WM + mt * 16 + gid;
                int col  = bn + warpN * WN + nt * 8 + 2 * tig;
                float a0x = 0.f, a0y = 0.f, a1x = 0.f, a1y = 0.f;
                if (addend) {
                    float2 v = *(const float2*)(addend + (size_t)row0 * ldadd + col);
                    a0x = v.x; a0y = v.y;
                    float2 w = *(const float2*)(addend + (size_t)(row0 + 8) * ldadd + col);
                    a1x = w.x; a1y = w.y;
                }
                __half2 h0 = __floats2half2_rn(acc[mt][nt][0] + a0x, acc[mt][nt][1] + a0y);
                __half2 h1 = __floats2half2_rn(acc[mt][nt][2] + a1x, acc[mt][nt][3] + a1y);
                *(__half2*)(C + (size_t)row0 * ldc + col) = h0;
                *(__half2*)(C + (size_t)(row0 + 8) * ldc + col) = h1;
            }
        }
    } else if constexpr (MODE == 2) {
        float* C = (float*)Cv;
#pragma unroll
        for (int mt = 0; mt < M_SUB; mt++) {
#pragma unroll
            for (int nt = 0; nt < N_SUB; nt++) {
                int row0 = bm + warpM * WM + mt * 16 + gid;
                int col  = bn + warpN * WN + nt * 8 + 2 * tig;
                float2 bv = *(const float2*)(bias + col);
#pragma unroll
                for (int rr = 0; rr < 2; rr++) {
                    int r = row0 + rr * 8;
                    int tt = r >> 9, b = r & 511;
                    float2 v = { acc[mt][nt][rr * 2 + 0] + bv.x,
                                 acc[mt][nt][rr * 2 + 1] + bv.y };
                    *(float2*)(C + ((size_t)b * TT + tt) * NCLS + col) = v;
                }
            }
        }
    } else {  // MODE 1: fused LSTM epilogue
        float* Cs = (float*)sh;
        constexpr int CPAD = 4;
        __syncthreads();
#pragma unroll
        for (int mt = 0; mt < M_SUB; mt++) {
#pragma unroll
            for (int nt = 0; nt < N_SUB; nt++) {
                int rl = warpM * WM + mt * 16 + gid;
                int cl = warpN * WN + nt * 8 + 2 * tig;
                float b0 = g_bg[bn + cl], b1 = g_bg[bn + cl + 1];
                Cs[rl * (BN + CPAD) + cl]           = acc[mt][nt][0] + b0;
                Cs[rl * (BN + CPAD) + cl + 1]       = acc[mt][nt][1] + b1;
                Cs[(rl + 8) * (BN + CPAD) + cl]     = acc[mt][nt][2] + b0;
                Cs[(rl + 8) * (BN + CPAD) + cl + 1] = acc[mt][nt][3] + b1;
            }
        }
        __syncthreads();
        constexpr int UNITS = BN / 4;
        for (int it = tid; it < BM * UNITS; it += THREADS) {
            int r = it / UNITS, u = it % UNITS;
            float gi = Cs[r * (BN + CPAD) + 4 * u + 0];
            float gf = Cs[r * (BN + CPAD) + 4 * u + 1];
            float gg = Cs[r * (BN + CPAD) + 4 * u + 2];
            float go = Cs[r * (BN + CPAD) + 4 * u + 3];
            int b = bm + r;
            int j = (bn >> 2) + u;
            int idx = b * HID + j;
            float c = g_c[idx];
            float cn = fsig(gf) * c + fsig(gi) * ftanh(gg);
            g_c[idx] = cn;
            __half hn = __float2half_rn(fsig(go) * ftanh(cn));
            h_out[idx] = hn;
            g_hist[(size_t)t * BATCH * HID + idx] = hn;
        }
    }
}

// ---- fused attention: softmax(logits) -> scores -> softmax_p -> ctx -------
__global__ void attention_kernel(const float* __restrict__ logits, __half* __restrict__ ctx)
{
    const int b = blockIdx.x;
    const int tid = threadIdx.x;  // 256
    const int lane = tid & 31, warp = tid >> 5;
    __shared__ float sa[HID];
    __shared__ float sw[NP];
    __shared__ float red[8];
    const float* fb = g_feats + (size_t)b * NP * HID;

    const float* x = logits + (size_t)b * HID;
    float v0 = x[tid], v1 = x[tid + 256];
    float m = fmaxf(v0, v1);
#pragma unroll
    for (int o = 16; o > 0; o >>= 1) m = fmaxf(m, __shfl_xor_sync(0xffffffffu, m, o));
    if (lane == 0) red[warp] = m;
    __syncthreads();
    if (tid == 0) {
        float tv = red[0];
#pragma unroll
        for (int i = 1; i < 8; i++) tv = fmaxf(tv, red[i]);
        red[0] = tv;
    }
    __syncthreads();
    m = red[0];
    __syncthreads();
    float e0 = __expf(v0 - m), e1 = __expf(v1 - m);
    float s = e0 + e1;
#pragma unroll
    for (int o = 16; o > 0; o >>= 1) s += __shfl_xor_sync(0xffffffffu, s, o);
    if (lane == 0) red[warp] = s;
    __syncthreads();
    if (tid == 0) {
        float tv = 0.f;
#pragma unroll
        for (int i = 0; i < 8; i++) tv += red[i];
        red[0] = tv;
    }
    __syncthreads();
    float inv = __fdividef(1.f, red[0]);
    sa[tid] = e0 * inv;
    sa[tid + 256] = e1 * inv;
    __syncthreads();

    const float4* sa4 = (const float4*)sa;
    for (int p = warp; p < NP; p += 8) {
        const float4* fr4 = (const float4*)(fb + (size_t)p * HID);
        float sc = 0.f;
#pragma unroll
        for (int e = lane; e < HID / 4; e += 32) {
            float4 f = __ldg(&fr4[e]);
            float4 a = sa4[e];
            sc += f.x * a.x + f.y * a.y + f.z * a.z + f.w * a.w;
        }
#pragma unroll
        for (int o = 16; o > 0; o >>= 1) sc += __shfl_xor_sync(0xffffffffu, sc, o);
        if (lane == 0) sw[p] = sc;
    }
    __syncthreads();

    if (tid < 32) {
        float w0 = sw[tid], w1 = sw[tid + 32];
        float mm = fmaxf(w0, w1);
#pragma unroll
        for (int o = 16; o > 0; o >>= 1) mm = fmaxf(mm, __shfl_xor_sync(0xffffffffu, mm, o));
        float f0 = __expf(w0 - mm), f1 = __expf(w1 - mm);
        float ss = f0 + f1;
#pragma unroll
        for (int o = 16; o > 0; o >>= 1) ss += __shfl_xor_sync(0xffffffffu, ss, o);
        float iv = __fdividef(1.f, ss);
        sw[tid] = f0 * iv;
        sw[tid + 32] = f1 * iv;
    }
    __syncthreads();

    const float2* fb2 = (const float2*)fb;
    float2 a2 = {0.f, 0.f};
#pragma unroll 8
    for (int p = 0; p < NP; p++) {
        float w = sw[p];
        float2 f = __ldg(&fb2[p * (HID / 2) + tid]);
        a2.x += w * f.x;
        a2.y += w * f.y;
    }
    *(__half2*)(ctx + (size_t)b * HID + 2 * tid) = __floats2half2_rn(a2.x, a2.y);
}

// ---------------- setup kernels -------------------------------------------
__global__ void zero_hc_kernel()
{
    int idx = blockIdx.x * blockDim.x + threadIdx.x;
    g_hbuf[0][idx] = __float2half_rn(0.f);
    g_c[idx] = 0.f;
}

__global__ void cvt_copy_kernel(const float* __restrict__ src, __half* __restrict__ dst, int n4)
{
    for (int i = blockIdx.x * blockDim.x + threadIdx.x; i < n4; i += gridDim.x * blockDim.x) {
        float4 v = ((const float4*)src)[i];
        __half2 h0 = __floats2half2_rn(v.x, v.y);
        __half2 h1 = __floats2half2_rn(v.z, v.w);
        *(uint2*)(dst + (size_t)i * 4) = make_uint2(
            *(uint32_t*)&h0, *(uint32_t*)&h1);
    }
}

// gate-interleaved Wg: row (4j+gi) = original row (gi*512+j); cols [Wih|Whh]
__global__ void build_wg_kernel(const float* __restrict__ Wih, const float* __restrict__ Whh,
                                const float* __restrict__ bih, const float* __restrict__ bhh)
{
    int idx = blockIdx.x * blockDim.x + threadIdx.x;
    int rn = idx >> 10, k = idx & 1023;
    int j = rn >> 2, gi = rn & 3;
    int orig = gi * 512 + j;
    float v = (k < 512) ? Wih[(size_t)orig * 512 + k] : Whh[(size_t)orig * 512 + (k - 512)];
    g_Wg[idx] = __float2half_rn(v);
    if (k == 0) g_bg[rn] = bih[orig] + bhh[orig];
}

__global__ void build_wlx_kernel(const float* __restrict__ Wa, const float* __restrict__ Wc,
                                 const float* __restrict__ ba, const float* __restrict__ bc)
{
    int idx = blockIdx.x * blockDim.x + threadIdx.x;
    int rn = idx >> 9, k = idx & 511;
    float v = (rn < 512) ? Wa[(size_t)rn * 1024 + 512 + k]
                         : Wc[(size_t)(rn - 512) * 1024 + k];
    g_Wlx[idx] = __float2half_rn(v);
    if (k == 0) g_blx[rn] = (rn < 512) ? ba[rn] : bc[rn - 512];
}

__global__ void gather_emb_kernel(const int* __restrict__ targets,
                                  const float* __restrict__ table)
{
    int b = blockIdx.x;
    int t = blockIdx.y;
    int id = (t == 0) ? 0 : targets[(size_t)b * TT + (t - 1)];
    const float4* src = (const float4*)(table + (size_t)id * EMB);
    __half* dst = g_emb + ((size_t)t * BATCH + b) * EMB;
    int e = threadIdx.x;  // 128 threads * 4 halfs
    float4 v = src[e];
    __half2 h0 = __floats2half2_rn(v.x, v.y);
    __half2 h1 = __floats2half2_rn(v.z, v.w);
    *(uint2*)(dst + e * 4) = make_uint2(*(uint32_t*)&h0, *(uint32_t*)&h1);
}

// ---------------- launch ----------------------------------------------------
extern "C" void kernel_launch(void* const* d_in, const int* in_sizes, int n_in,
                              void* d_out, int out_size)
{
    const float* features  = (const float*)d_in[0];
    const int*   targets   = (const int*)d_in[1];
    const float* Wfc = (const float*)d_in[3];
    const float* bfc = (const float*)d_in[4];
    const float* emb_table = (const float*)d_in[5];
    const float* Wa  = (const float*)d_in[6];
    const float* ba  = (const float*)d_in[7];
    const float* Wc  = (const float*)d_in[8];
    const float* bc  = (const float*)d_in[9];
    const float* Wih = (const float*)d_in[10];
    const float* Whh = (const float*)d_in[11];
    const float* bih = (const float*)d_in[12];
    const float* bhh = (const float*)d_in[13];
    const float* Wo  = (const float*)d_in[14];
    const float* bo  = (const float*)d_in[15];
    float* out = (float*)d_out;

    __half *p_featcvt, *p_emb, *p_hist, *p_hbuf, *p_ctx, *p_x, *p_Wg, *p_Wlx, *p_wcvt;
    float *p_feats, *p_pre, *p_logits, *p_blx;
    cudaGetSymbolAddress((void**)&p_featcvt, g_featcvt);
    cudaGetSymbolAddress((void**)&p_feats,   g_feats);
    cudaGetSymbolAddress((void**)&p_emb,     g_emb);
    cudaGetSymbolAddress((void**)&p_pre,     g_pre);
    cudaGetSymbolAddress((void**)&p_hist,    g_hist);
    cudaGetSymbolAddress((void**)&p_hbuf,    g_hbuf);
    cudaGetSymbolAddress((void**)&p_logits,  g_logits);
    cudaGetSymbolAddress((void**)&p_ctx,     g_ctx);
    cudaGetSymbolAddress((void**)&p_x,       g_x);
    cudaGetSymbolAddress((void**)&p_Wg,      g_Wg);
    cudaGetSymbolAddress((void**)&p_Wlx,     g_Wlx);
    cudaGetSymbolAddress((void**)&p_blx,     g_blx);
    cudaGetSymbolAddress((void**)&p_wcvt,    g_wcvt);

    constexpr int SM_BIG   = 3 * (128 + 64) * 72 * 2;   // 82944
    constexpr int SM_SMALL = 3 * (64 + 32) * 72 * 2;    // 41472
    constexpr int SM_OUT   = 3 * (128 + 32) * 72 * 2;   // 69120

    cudaFuncSetAttribute((const void*)gemm<128, 64, 64, 4, 2, 0>,
                         cudaFuncAttributeMaxDynamicSharedMemorySize, SM_BIG);
    cudaFuncSetAttribute((const void*)gemm<128, 64, 64, 4, 2, 1>,
                         cudaFuncAttributeMaxDynamicSharedMemorySize, SM_BIG);
    cudaFuncSetAttribute((const void*)gemm<64, 32, 64, 2, 2, 0>,
                         cudaFuncAttributeMaxDynamicSharedMemorySize, SM_SMALL);
    cudaFuncSetAttribute((const void*)gemm<64, 32, 64, 2, 2, 3>,
                         cudaFuncAttributeMaxDynamicSharedMemorySize, SM_SMALL);
    cudaFuncSetAttribute((const void*)gemm<128, 32, 64, 4, 1, 2>,
                         cudaFuncAttributeMaxDynamicSharedMemorySize, SM_OUT);

    // setup
    zero_hc_kernel<<<(BATCH * HID) / 256, 256>>>();
    build_wg_kernel<<<(2048 * 1024) / 256, 256>>>(Wih, Whh, bih, bhh);
    build_wlx_kernel<<<(1024 * 512) / 256, 256>>>(Wa, Wc, ba, bc);
    gather_emb_kernel<<<dim3(BATCH, TT), 128>>>(targets, emb_table);
    cvt_copy_kernel<<<1024, 256>>>(features, p_featcvt, BATCH * NP * CIN / 4);
    cvt_copy_kernel<<<256, 256>>>(Wfc, p_wcvt + OFF_WFC, 512 * 512 / 4);
    cvt_copy_kernel<<<512, 256>>>(Wa,  p_wcvt + OFF_WA,  512 * 1024 / 4);
    cvt_copy_kernel<<<512, 256>>>(Wc,  p_wcvt + OFF_WC,  512 * 1024 / 4);
    cvt_copy_kernel<<<64, 256>>>(Wo,   p_wcvt + OFF_WO,  96 * 512 / 4);

    // feats = features @ Wfc^T + bfc : M=32768, N=512, K=512 (fp32 out)
    gemm<128, 64, 64, 4, 2, 0><<<dim3(HID / 64, (BATCH * NP) / 128), 256, SM_BIG>>>(
        p_featcvt, CIN, CIN, nullptr, 0, CIN,
        p_wcvt + OFF_WFC, CIN, 0, bfc, nullptr, 0, p_feats, HID, nullptr, 0);

    // pre = emb @ [WaE;WcC]^T + [ba;bc] : M=15360, N=1024, K=512 (fp32 out)
    gemm<128, 64, 64, 4, 2, 0><<<dim3(1024 / 64, (TT * BATCH) / 128), 256, SM_BIG>>>(
        p_emb, EMB, EMB, nullptr, 0, EMB,
        p_Wlx, 512, 0, p_blx, nullptr, 0, p_pre, 1024, nullptr, 0);

    for (int t = 0; t < TT; t++) {
        __half* hr = p_hbuf + (t & 1) * BATCH * HID;
        __half* hw = p_hbuf + ((t + 1) & 1) * BATCH * HID;
        const float* pre_t = p_pre + (size_t)t * BATCH * 1024;

        // logits = h @ Wa[:,:512]^T + pre[t][:, :512]  (fp32 out)
        gemm<64, 32, 64, 2, 2, 0><<<dim3(HID / 32, BATCH / 64), 128, SM_SMALL>>>(
            hr, HID, HID, nullptr, 0, HID,
            p_wcvt + OFF_WA, HID + EMB, 0, nullptr, pre_t, 1024,
            p_logits, HID, nullptr, 0);

        attention_kernel<<<BATCH, 256>>>(p_logits, p_ctx);

        // x = ctx @ Wc[:,512:]^T + pre[t][:, 512:]  (half out)
        gemm<64, 32, 64, 2, 2, 3><<<dim3(HID / 32, BATCH / 64), 128, SM_SMALL>>>(
            p_ctx, HID, HID, nullptr, 0, HID,
            p_wcvt + OFF_WC, EMB + HID, 512, nullptr, pre_t + 512, 1024,
            p_x, HID, nullptr, 0);

        // gates = [x,h] @ Wg^T + bg ; fused LSTM; writes hw, g_c, g_hist[t]
        gemm<128, 64, 64, 4, 2, 1><<<dim3((4 * HID) / 64, BATCH / 128), 256, SM_BIG>>>(
            p_x, HID, HID, hr, HID, 2 * HID,
            p_Wg, 2 * HID, 0, nullptr, nullptr, 0, nullptr, 0, hw, t);
    }

    // out[b,t,:] = hist @ Wo^T + bo : M=15360, N=96, K=512, permuted write
    gemm<128, 32, 64, 4, 1, 2><<<dim3(NCLS / 32, (TT * BATCH) / 128), 128, SM_OUT>>>(
        p_hist, HID, HID, nullptr, 0, HID,
        p_wcvt + OFF_WO, HID, 0, bo, nullptr, 0, out, 0, nullptr, 0);
}